// round 9
// baseline (speedup 1.0000x reference)
#include <cuda_runtime.h>
#include <math.h>

#define C        144
#define W        77
#define KW       10
#define FC       64
#define CONV_OUT 68                    // W - KW + 1
#define CONCAT   (C*FC + CONV_OUT)     // 9284
#define H2       128
#define GRID     C                     // one block per channel, 1 per SM
#define NT       1024                  // 32 warps per block
#define PAD      64                    // 256 B accumulator stride (L2 slice spread)

// Scratch (no device allocation allowed); zeroed at load, reset by last block.
__device__ __align__(256) float g_hp[H2 * PAD];          // 32 KB
__device__ __align__(256) float g_convp[CONV_OUT * PAD]; // 17 KB
__device__ unsigned int g_cnt = 0u;

__device__ __forceinline__ float warp_reduce(float v) {
#pragma unroll
    for (int o = 16; o > 0; o >>= 1) v += __shfl_down_sync(0xffffffffu, v, o);
    return v;
}

__device__ __forceinline__ float dot4(float4 a, float4 b) {
    return a.x * b.x + a.y * b.y + a.z * b.z + a.w * b.w;
}

// ---------------------------------------------------------------------------
// Barrier-minimal fused kernel, one 1024-thread block per channel.
//   ALL global loads are front-batched into registers at kernel entry
//   (w2 slice, fc_w operands, per-warp x slice) -> FC runs with NO barrier.
//   Single mid-kernel __syncthreads before the w2-dot + conv stage.
//   Padded atomics (256 B stride) spread REDs across L2 slices.
//   Last block (counter) does conv matvec + final layers + scratch reset.
// ---------------------------------------------------------------------------
__global__ __launch_bounds__(NT, 1) void fused_kernel(
    const float* __restrict__ x,       // [C, W]
    const float* __restrict__ fc_w,    // [C, FC, W]
    const float* __restrict__ fc_b,    // [C, FC]
    const float* __restrict__ conv_w,  // [C, KW]
    const float* __restrict__ conv_b,  // [1]
    const float* __restrict__ w2,      // [H2, CONCAT]
    const float* __restrict__ b2,      // [H2]
    const float* __restrict__ w3,      // [1, H2]
    const float* __restrict__ b3,      // [1]
    float* __restrict__ out)           // [1]
{
    const int tid  = threadIdx.x;
    const int lane = tid & 31;
    const int warp = tid >> 5;
    const int c    = blockIdx.x;

    const int j = tid >> 3;            // 0..127 : w2 row owned by this thread
    const int p = tid & 7;             // 0..7   : position within row group

    __shared__ float xs[W];
    __shared__ float cw[KW];
    __shared__ __align__(16) float vals[FC];
    __shared__ __align__(16) float convv[CONV_OUT];
    __shared__ float sm_h[H2];
    __shared__ unsigned int s_last;

    // =============== front-batched global loads (max MLP) ===============
    const bool tail = (lane < W - 64);                   // 13-element tail

    // (1) w2 FC slice: row j cols [c*64, +64) = 16 float4; 8 th/row, 2 each
    const float4* wrow = reinterpret_cast<const float4*>(
        w2 + (size_t)j * CONCAT + c * FC);
    const float4 a0 = wrow[p];
    const float4 a1 = wrow[p + 8];

    // (2) per-warp x slice (redundant across warps; tiny + L2-hot)
    const float* xr = x + c * W;
    const float x0 = xr[lane];
    const float x1 = xr[lane + 32];
    const float x2 = tail ? xr[lane + 64] : 0.f;

    // (3) fc_w operands for this warp's 2 outputs
    const int d0 = warp * 2;
    const float* r0 = fc_w + (size_t)(c * FC + d0) * W;
    const float* r1 = r0 + W;
    const float f00 = r0[lane], f01 = r0[lane + 32], f02 = tail ? r0[lane + 64] : 0.f;
    const float f10 = r1[lane], f11 = r1[lane + 32], f12 = tail ? r1[lane + 64] : 0.f;

    // (4) xs / conv weights into smem (consumed after the single barrier)
    if (tid < W)               xs[tid]     = xr[tid];
    else if (tid < W + KW)     cw[tid - W] = conv_w[c * KW + (tid - W)];

    // =================== FC: no barrier needed ===========================
    {
        float s0 = f00 * x0 + f01 * x1 + f02 * x2;
        float s1 = f10 * x0 + f11 * x1 + f12 * x2;
        s0 = warp_reduce(s0);
        s1 = warp_reduce(s1);
        if (lane == 0) {
            vals[d0]     = s0 + fc_b[c * FC + d0];
            vals[d0 + 1] = s1 + fc_b[c * FC + d0 + 1];
        }
    }

    __syncthreads();                   // vals[] and xs[]/cw[] now visible

    // ---------------- conv contribution (padded RED) ---------------------
    if (tid < CONV_OUT) {
        float s = 0.f;
#pragma unroll
        for (int k = 0; k < KW; k++) s += xs[tid + k] * cw[k];
        atomicAdd(&g_convp[tid * PAD], s);
    }

    // -------------- g_hp[j*PAD] += w2_slice[j,:] . vals ------------------
    {
        const float4* v4 = reinterpret_cast<const float4*>(vals);
        float s = dot4(a0, v4[p]) + dot4(a1, v4[p + 8]);
#pragma unroll
        for (int o = 4; o > 0; o >>= 1)
            s += __shfl_down_sync(0xffffffffu, s, o, 8);
        if (p == 0) {
            atomicAdd(&g_hp[j * PAD], s);
            __threadfence();           // release my RED before my arrive
        }
    }

    // ---- last-block election (no spinning; non-last blocks exit) --------
    __syncthreads();
    if (tid == 0)
        s_last = (atomicAdd(&g_cnt, 1u) == GRID - 1) ? 1u : 0u;
    __syncthreads();
    if (s_last == 0u) return;

    // =================== finalization (last block only) ==================
    __threadfence();                   // acquire all g_hp / g_convp updates

    if (tid < CONV_OUT) {
        convv[tid]          = g_convp[tid * PAD] + conv_b[0];
        g_convp[tid * PAD]  = 0.f;     // reset for next replay
    }
    __syncthreads();

    // conv matvec: h[j] += w2[j, 9216:9284] . convv ; then relu & w3 weight
    {
        const float4* rw = reinterpret_cast<const float4*>(
            w2 + (size_t)j * CONCAT + C * FC);           // 16B-aligned
        const float4* cv = reinterpret_cast<const float4*>(convv);
        float s = dot4(rw[p], cv[p]) + dot4(rw[p + 8], cv[p + 8]);
        if (p == 0) s += dot4(rw[16], cv[16]);           // 17th float4
#pragma unroll
        for (int o = 4; o > 0; o >>= 1)
            s += __shfl_down_sync(0xffffffffu, s, o, 8);
        if (p == 0) {
            const float pre = g_hp[j * PAD] + s + b2[j];
            sm_h[j] = fmaxf(pre, 0.f) * w3[j];
            g_hp[j * PAD] = 0.f;       // reset for next replay
        }
    }
    __syncthreads();

    if (warp == 0) {
        float v = sm_h[lane] + sm_h[lane + 32]
                + sm_h[lane + 64] + sm_h[lane + 96];
        v = warp_reduce(v);
        if (lane == 0) {
            const float o2 = fmaxf(v + b3[0], 0.f);
            out[0] = 1.f / (1.f + __expf(-o2));
            g_cnt  = 0u;               // reset for next replay
        }
    }
}

// ---------------------------------------------------------------------------
extern "C" void kernel_launch(void* const* d_in, const int* in_sizes, int n_in,
                              void* d_out, int out_size) {
    const float* x      = (const float*)d_in[0];
    const float* fc_w   = (const float*)d_in[1];
    const float* fc_b   = (const float*)d_in[2];
    const float* conv_w = (const float*)d_in[3];
    const float* conv_b = (const float*)d_in[4];
    const float* w2     = (const float*)d_in[5];
    const float* b2     = (const float*)d_in[6];
    const float* w3     = (const float*)d_in[7];
    const float* b3     = (const float*)d_in[8];

    fused_kernel<<<GRID, NT>>>(x, fc_w, fc_b, conv_w, conv_b,
                               w2, b2, w3, b3, (float*)d_out);
}